// round 1
// baseline (speedup 1.0000x reference)
#include <cuda_runtime.h>
#include <cuda_bf16.h>

#define NN   10000
#define NE   320000
#define FIN  512
#define F    64

#define MU_OFF  ((size_t)NN * (size_t)NN)
#define STD_OFF (MU_OFF + (size_t)NN * F)

// ---------------- scratch (device globals; no allocation allowed) ----------
__device__ float g_P[NN * F];        // feat @ W1
__device__ float g_h1n[NN * F];      // h1 * rsqrt(deg_out)  (input to layer 2/3 projections)
__device__ float g_hms[NN * 2 * F];  // [h1n@Wmu | h1n@Wstd]
__device__ float g_zT[F * NN];       // z transposed (64 x 10000) for the SYRK
__device__ float g_sout[NN];
__device__ float g_sin[NN];
__device__ int   g_cout[NN];
__device__ int   g_cin[NN];
__device__ int   g_off[NN];
__device__ int   g_cur[NN];
__device__ int   g_esrc[NE];

// ---------------- small helpers -------------------------------------------
__device__ __forceinline__ float sigf(float x) {
    return __fdividef(1.0f, 1.0f + __expf(-x));
}

// ---------------- graph preprocessing -------------------------------------
__global__ void k_zero() {
    int i = blockIdx.x * blockDim.x + threadIdx.x;
    if (i < NN) { g_cout[i] = 0; g_cin[i] = 0; }
}

__global__ void k_deg(const int* __restrict__ src, const int* __restrict__ dst) {
    int e = blockIdx.x * blockDim.x + threadIdx.x;
    if (e < NE) {
        atomicAdd(&g_cout[src[e]], 1);
        atomicAdd(&g_cin[dst[e]], 1);
    }
}

// single block: exclusive scan of in-degrees -> offsets & cursors; also scales
__global__ __launch_bounds__(1024) void k_scan() {
    __shared__ int part[1024];
    int t = threadIdx.x;
    const int chunk = (NN + 1023) / 1024;  // 10
    int beg = t * chunk;
    int end = beg + chunk; if (end > NN) end = NN;
    int mysum = 0;
    for (int i = beg; i < end && i < NN; i++) mysum += g_cin[i];
    part[t] = mysum;
    __syncthreads();
    for (int d = 1; d < 1024; d <<= 1) {
        int v = (t >= d) ? part[t - d] : 0;
        __syncthreads();
        part[t] += v;
        __syncthreads();
    }
    int prefix = part[t] - mysum;
    for (int i = beg; i < end && i < NN; i++) {
        int c = g_cin[i];
        g_off[i] = prefix;
        g_cur[i] = prefix;
        prefix += c;
        int co = g_cout[i]; if (co < 1) co = 1;
        int ci = g_cin[i];  if (ci < 1) ci = 1;
        g_sout[i] = rsqrtf((float)co);
        g_sin[i]  = rsqrtf((float)ci);
    }
}

__global__ void k_scatter(const int* __restrict__ src, const int* __restrict__ dst) {
    int e = blockIdx.x * blockDim.x + threadIdx.x;
    if (e < NE) {
        int p = atomicAdd(&g_cur[dst[e]], 1);
        g_esrc[p] = src[e];
    }
}

// ---------------- GEMM1: P = feat @ W1  (10000 x 512 x 64) ----------------
__global__ __launch_bounds__(256) void k_gemm1(const float* __restrict__ feat,
                                               const float* __restrict__ W1) {
    __shared__ float sA[64][68];   // [row][k]
    __shared__ float sB[64][64];   // [k][col]
    int tid = threadIdx.x;
    int tx = tid & 15, ty = tid >> 4;
    int rowBase = blockIdx.x * 64;
    float acc[4][4] = {};
    for (int kt = 0; kt < FIN; kt += 64) {
#pragma unroll
        for (int it = 0; it < 4; it++) {
            int r = ty + it * 16;
            int gr = rowBase + r;
            float4 v = make_float4(0.f, 0.f, 0.f, 0.f);
            if (gr < NN) v = *(const float4*)(feat + (size_t)gr * FIN + kt + tx * 4);
            *(float4*)&sA[r][tx * 4] = v;
            *(float4*)&sB[r][tx * 4] = *(const float4*)(W1 + (size_t)(kt + r) * F + tx * 4);
        }
        __syncthreads();
#pragma unroll 16
        for (int kk = 0; kk < 64; kk++) {
            float a0 = sA[ty * 4 + 0][kk];
            float a1 = sA[ty * 4 + 1][kk];
            float a2 = sA[ty * 4 + 2][kk];
            float a3 = sA[ty * 4 + 3][kk];
            float4 b = *(float4*)&sB[kk][tx * 4];
            acc[0][0] += a0 * b.x; acc[0][1] += a0 * b.y; acc[0][2] += a0 * b.z; acc[0][3] += a0 * b.w;
            acc[1][0] += a1 * b.x; acc[1][1] += a1 * b.y; acc[1][2] += a1 * b.z; acc[1][3] += a1 * b.w;
            acc[2][0] += a2 * b.x; acc[2][1] += a2 * b.y; acc[2][2] += a2 * b.z; acc[2][3] += a2 * b.w;
            acc[3][0] += a3 * b.x; acc[3][1] += a3 * b.y; acc[3][2] += a3 * b.z; acc[3][3] += a3 * b.w;
        }
        __syncthreads();
    }
#pragma unroll
    for (int i = 0; i < 4; i++) {
        int r = rowBase + ty * 4 + i;
        if (r < NN) {
            float4 v = make_float4(acc[i][0], acc[i][1], acc[i][2], acc[i][3]);
            *(float4*)&g_P[r * F + tx * 4] = v;
        }
    }
}

// ---------------- gather 1: h1n = ((sum s_out[s]*P[s]) * s_in + b1) * s_out -
__global__ __launch_bounds__(256) void k_gather1(const float* __restrict__ b1) {
    int node = blockIdx.x * 8 + (threadIdx.x >> 5);
    if (node >= NN) return;
    int lane = threadIdx.x & 31;
    int beg = g_off[node];
    int cnt = g_cin[node];
    float a0 = 0.f, a1 = 0.f;
    int j = 0;
    for (; j + 4 <= cnt; j += 4) {
        int s0 = g_esrc[beg + j + 0];
        int s1 = g_esrc[beg + j + 1];
        int s2 = g_esrc[beg + j + 2];
        int s3 = g_esrc[beg + j + 3];
        float w0 = g_sout[s0], w1 = g_sout[s1], w2 = g_sout[s2], w3 = g_sout[s3];
        a0 += w0 * g_P[s0 * F + lane];      a1 += w0 * g_P[s0 * F + 32 + lane];
        a0 += w1 * g_P[s1 * F + lane];      a1 += w1 * g_P[s1 * F + 32 + lane];
        a0 += w2 * g_P[s2 * F + lane];      a1 += w2 * g_P[s2 * F + 32 + lane];
        a0 += w3 * g_P[s3 * F + lane];      a1 += w3 * g_P[s3 * F + 32 + lane];
    }
    for (; j < cnt; j++) {
        int s = g_esrc[beg + j];
        float w = g_sout[s];
        a0 += w * g_P[s * F + lane];
        a1 += w * g_P[s * F + 32 + lane];
    }
    float si = g_sin[node];
    float h0 = a0 * si + b1[lane];
    float h1 = a1 * si + b1[lane + 32];
    float so = g_sout[node];
    g_h1n[node * F + lane]       = h0 * so;
    g_h1n[node * F + 32 + lane]  = h1 * so;
}

// ---------------- GEMM2: hms = h1n @ [Wmu | Wstd]  (10000 x 64 x 128) ------
__global__ __launch_bounds__(256) void k_gemm2(const float* __restrict__ Wmu,
                                               const float* __restrict__ Wstd) {
    __shared__ float sA[64][64];    // [row][k]
    __shared__ float sW[64][128];   // [k][col]  (mu cols 0..63, std 64..127)
    int tid = threadIdx.x;
    int tx = tid & 15, ty = tid >> 4;
    int rowBase = blockIdx.x * 64;
    {
        int f4c = tid & 31;
        int k0 = tid >> 5;
#pragma unroll
        for (int it = 0; it < 8; it++) {
            int k = k0 + it * 8;
            float4 w;
            if (f4c < 16) w = *(const float4*)(Wmu + k * F + f4c * 4);
            else          w = *(const float4*)(Wstd + k * F + (f4c - 16) * 4);
            *(float4*)&sW[k][f4c * 4] = w;
        }
    }
#pragma unroll
    for (int it = 0; it < 4; it++) {
        int r = ty + it * 16;
        int gr = rowBase + r;
        float4 v = make_float4(0.f, 0.f, 0.f, 0.f);
        if (gr < NN) v = *(const float4*)&g_h1n[gr * F + tx * 4];
        *(float4*)&sA[r][tx * 4] = v;
    }
    __syncthreads();
    float acc[4][8] = {};
#pragma unroll 8
    for (int kk = 0; kk < 64; kk++) {
        float a0 = sA[ty * 4 + 0][kk];
        float a1 = sA[ty * 4 + 1][kk];
        float a2 = sA[ty * 4 + 2][kk];
        float a3 = sA[ty * 4 + 3][kk];
        float4 b0 = *(float4*)&sW[kk][tx * 8];
        float4 b1 = *(float4*)&sW[kk][tx * 8 + 4];
        acc[0][0] += a0 * b0.x; acc[0][1] += a0 * b0.y; acc[0][2] += a0 * b0.z; acc[0][3] += a0 * b0.w;
        acc[0][4] += a0 * b1.x; acc[0][5] += a0 * b1.y; acc[0][6] += a0 * b1.z; acc[0][7] += a0 * b1.w;
        acc[1][0] += a1 * b0.x; acc[1][1] += a1 * b0.y; acc[1][2] += a1 * b0.z; acc[1][3] += a1 * b0.w;
        acc[1][4] += a1 * b1.x; acc[1][5] += a1 * b1.y; acc[1][6] += a1 * b1.z; acc[1][7] += a1 * b1.w;
        acc[2][0] += a2 * b0.x; acc[2][1] += a2 * b0.y; acc[2][2] += a2 * b0.z; acc[2][3] += a2 * b0.w;
        acc[2][4] += a2 * b1.x; acc[2][5] += a2 * b1.y; acc[2][6] += a2 * b1.z; acc[2][7] += a2 * b1.w;
        acc[3][0] += a3 * b0.x; acc[3][1] += a3 * b0.y; acc[3][2] += a3 * b0.z; acc[3][3] += a3 * b0.w;
        acc[3][4] += a3 * b1.x; acc[3][5] += a3 * b1.y; acc[3][6] += a3 * b1.z; acc[3][7] += a3 * b1.w;
    }
#pragma unroll
    for (int i = 0; i < 4; i++) {
        int r = rowBase + ty * 4 + i;
        if (r < NN) {
            *(float4*)&g_hms[r * 128 + tx * 8]     = make_float4(acc[i][0], acc[i][1], acc[i][2], acc[i][3]);
            *(float4*)&g_hms[r * 128 + tx * 8 + 4] = make_float4(acc[i][4], acc[i][5], acc[i][6], acc[i][7]);
        }
    }
}

// ---------------- gather 2: mu/std/z ---------------------------------------
__global__ __launch_bounds__(256) void k_gather2(const float* __restrict__ eps,
                                                 const float* __restrict__ bmu,
                                                 const float* __restrict__ bstd,
                                                 float* __restrict__ out) {
    int node = blockIdx.x * 8 + (threadIdx.x >> 5);
    if (node >= NN) return;
    int lane = threadIdx.x & 31;
    int beg = g_off[node];
    int cnt = g_cin[node];
    float m0 = 0.f, m1 = 0.f, v0 = 0.f, v1 = 0.f;
    int j = 0;
    for (; j + 2 <= cnt; j += 2) {
        int s0 = g_esrc[beg + j];
        int s1 = g_esrc[beg + j + 1];
        const float* p0 = &g_hms[s0 * 128];
        const float* p1 = &g_hms[s1 * 128];
        m0 += p0[lane];       m1 += p0[32 + lane];
        v0 += p0[64 + lane];  v1 += p0[96 + lane];
        m0 += p1[lane];       m1 += p1[32 + lane];
        v0 += p1[64 + lane];  v1 += p1[96 + lane];
    }
    for (; j < cnt; j++) {
        int s = g_esrc[beg + j];
        const float* p = &g_hms[s * 128];
        m0 += p[lane];       m1 += p[32 + lane];
        v0 += p[64 + lane];  v1 += p[96 + lane];
    }
    float si = g_sin[node];
    float mu0 = m0 * si + bmu[lane];
    float mu1 = m1 * si + bmu[lane + 32];
    float st0 = __expf(v0 * si + bstd[lane]);
    float st1 = __expf(v1 * si + bstd[lane + 32]);
    out[MU_OFF + (size_t)node * F + lane]       = mu0;
    out[MU_OFF + (size_t)node * F + 32 + lane]  = mu1;
    out[STD_OFF + (size_t)node * F + lane]      = st0;
    out[STD_OFF + (size_t)node * F + 32 + lane] = st1;
    float z0 = eps[node * F + lane]      * st0 + mu0;
    float z1 = eps[node * F + 32 + lane] * st1 + mu1;
    // transposed store for the SYRK (column-major over nodes)
    g_zT[lane * NN + node]        = z0;
    g_zT[(lane + 32) * NN + node] = z1;
}

// ---------------- adj = sigmoid(z @ z^T) : 128x128 tiles, f32x2 FMA --------
#define ADJ_S 132                           // padded tile row stride (floats)
#define ADJ_SMEM (2 * 64 * ADJ_S * 4)       // 67584 bytes

__global__ __launch_bounds__(256, 2) void k_adj(float* __restrict__ out) {
    extern __shared__ float smem[];
    float* sA = smem;                 // [64][ADJ_S]  A[k][i]
    float* sB = smem + 64 * ADJ_S;    // [64][ADJ_S]  B[k][j]

    int tid = threadIdx.x;
    int tx = tid & 15, ty = tid >> 4;
    int rb = blockIdx.y * 128;
    int cb = blockIdx.x * 128;

    // load both tiles directly from the transposed z: coalesced, no smem transpose
    {
        int f4c = tid & 31;     // 0..31 -> 128 cols per row
        int k0 = tid >> 5;      // 0..7
#pragma unroll
        for (int it = 0; it < 8; it++) {
            int k = k0 + it * 8;
            const float* rowp = g_zT + (size_t)k * NN;
            int ca = rb + f4c * 4;
            int cc = cb + f4c * 4;
            float4 va = (ca < NN) ? *(const float4*)(rowp + ca) : make_float4(0.f, 0.f, 0.f, 0.f);
            float4 vb = (cc < NN) ? *(const float4*)(rowp + cc) : make_float4(0.f, 0.f, 0.f, 0.f);
            *(float4*)&sA[k * ADJ_S + f4c * 4] = va;
            *(float4*)&sB[k * ADJ_S + f4c * 4] = vb;
        }
    }
    __syncthreads();

    int iy = ty * 8, jx = tx * 8;
    unsigned long long acc[8][4];
#pragma unroll
    for (int i = 0; i < 8; i++)
#pragma unroll
        for (int jp = 0; jp < 4; jp++) acc[i][jp] = 0ULL;

#pragma unroll 8
    for (int k = 0; k < 64; k++) {
        float a[8];
        *(float4*)&a[0] = *(float4*)&sA[k * ADJ_S + iy];
        *(float4*)&a[4] = *(float4*)&sA[k * ADJ_S + iy + 4];
        ulonglong2 b01 = *(ulonglong2*)&sB[k * ADJ_S + jx];
        ulonglong2 b23 = *(ulonglong2*)&sB[k * ADJ_S + jx + 4];
        unsigned long long bb0 = b01.x, bb1 = b01.y, bb2 = b23.x, bb3 = b23.y;
#pragma unroll
        for (int i = 0; i < 8; i++) {
            unsigned long long ad;
            asm("mov.b64 %0, {%1, %1};" : "=l"(ad) : "f"(a[i]));
            asm("fma.rn.f32x2 %0, %1, %2, %0;" : "+l"(acc[i][0]) : "l"(ad), "l"(bb0));
            asm("fma.rn.f32x2 %0, %1, %2, %0;" : "+l"(acc[i][1]) : "l"(ad), "l"(bb1));
            asm("fma.rn.f32x2 %0, %1, %2, %0;" : "+l"(acc[i][2]) : "l"(ad), "l"(bb2));
            asm("fma.rn.f32x2 %0, %1, %2, %0;" : "+l"(acc[i][3]) : "l"(ad), "l"(bb3));
        }
    }

    int gcol = cb + jx;
    bool colsOK = (gcol + 7 < NN);
#pragma unroll
    for (int i = 0; i < 8; i++) {
        int gr = rb + iy + i;
        if (gr >= NN) continue;
        float v[8];
#pragma unroll
        for (int jp = 0; jp < 4; jp++) {
            float lo, hi;
            asm("mov.b64 {%0, %1}, %2;" : "=f"(lo), "=f"(hi) : "l"(acc[i][jp]));
            v[2 * jp]     = sigf(lo);
            v[2 * jp + 1] = sigf(hi);
        }
        size_t base = (size_t)gr * NN + gcol;
        if (colsOK) {
            *(float4*)(out + base)     = make_float4(v[0], v[1], v[2], v[3]);
            *(float4*)(out + base + 4) = make_float4(v[4], v[5], v[6], v[7]);
        } else {
#pragma unroll
            for (int u = 0; u < 8; u++)
                if (gcol + u < NN) out[base + u] = v[u];
        }
    }
}

// ---------------- launcher -------------------------------------------------
extern "C" void kernel_launch(void* const* d_in, const int* in_sizes, int n_in,
                              void* d_out, int out_size) {
    (void)in_sizes; (void)n_in; (void)out_size;
    const float* feat = (const float*)d_in[0];
    const float* eps  = (const float*)d_in[1];
    const int*   src  = (const int*)d_in[2];
    const int*   dst  = (const int*)d_in[3];
    const float* W1   = (const float*)d_in[4];
    const float* b1   = (const float*)d_in[5];
    const float* Wmu  = (const float*)d_in[6];
    const float* bmu  = (const float*)d_in[7];
    const float* Wstd = (const float*)d_in[8];
    const float* bstd = (const float*)d_in[9];
    float* out = (float*)d_out;

    cudaFuncSetAttribute(k_adj, cudaFuncAttributeMaxDynamicSharedMemorySize, ADJ_SMEM);

    k_zero<<<(NN + 255) / 256, 256>>>();
    k_deg<<<NE / 256, 256>>>(src, dst);
    k_scan<<<1, 1024>>>();
    k_scatter<<<NE / 256, 256>>>(src, dst);
    k_gemm1<<<(NN + 63) / 64, 256>>>(feat, W1);
    k_gather1<<<(NN + 7) / 8, 256>>>(b1);
    k_gemm2<<<(NN + 63) / 64, 256>>>(Wmu, Wstd);
    k_gather2<<<(NN + 7) / 8, 256>>>(eps, bmu, bstd, out);
    dim3 grid((NN + 127) / 128, (NN + 127) / 128);
    k_adj<<<grid, 256, ADJ_SMEM>>>(out);
}

// round 3
// speedup vs baseline: 1.0419x; 1.0419x over previous
#include <cuda_runtime.h>
#include <cuda_bf16.h>
#include <cstdint>

#define NN   10000
#define NE   320000
#define FIN  512
#define F    64

#define MU_OFF  ((size_t)NN * (size_t)NN)
#define STD_OFF (MU_OFF + (size_t)NN * F)

// ---------------- scratch (device globals; no allocation allowed) ----------
__device__ float g_P[NN * F];        // feat @ W1
__device__ float g_h1n[NN * F];      // h1 * rsqrt(deg_out)
__device__ float g_hms[NN * 2 * F];  // [h1n@Wmu | h1n@Wstd]
__device__ __nv_bfloat16 g_ZA[NN * 192];  // [h | l | h]
__device__ __nv_bfloat16 g_ZB[NN * 192];  // [h | h | l]
__device__ float g_sout[NN];
__device__ float g_sin[NN];
__device__ int   g_cout[NN];
__device__ int   g_cin[NN];
__device__ int   g_off[NN];
__device__ int   g_cur[NN];
__device__ int   g_esrc[NE];

// ---------------- helpers ----------------------------------------------------
__device__ __forceinline__ uint32_t smem_u32(const void* p) {
    uint32_t a;
    asm("{ .reg .u64 t; cvta.to.shared.u64 t, %1; cvt.u32.u64 %0, t; }" : "=r"(a) : "l"(p));
    return a;
}
__device__ __forceinline__ void ldsm4(uint32_t* r, uint32_t addr) {
    asm volatile("ldmatrix.sync.aligned.m8n8.x4.shared.b16 {%0,%1,%2,%3}, [%4];"
        : "=r"(r[0]), "=r"(r[1]), "=r"(r[2]), "=r"(r[3]) : "r"(addr));
}
__device__ __forceinline__ void mma16816(float* d, const uint32_t* a, const uint32_t* b) {
    asm volatile("mma.sync.aligned.m16n8k16.row.col.f32.bf16.bf16.f32 "
        "{%0,%1,%2,%3},{%4,%5,%6,%7},{%8,%9},{%0,%1,%2,%3};"
        : "+f"(d[0]), "+f"(d[1]), "+f"(d[2]), "+f"(d[3])
        : "r"(a[0]), "r"(a[1]), "r"(a[2]), "r"(a[3]), "r"(b[0]), "r"(b[1]));
}
__device__ __forceinline__ float sigf(float x) {
    return __fdividef(1.0f, 1.0f + __expf(-x));
}

// ---------------- graph preprocessing -------------------------------------
__global__ void k_zero() {
    int i = blockIdx.x * blockDim.x + threadIdx.x;
    if (i < NN) { g_cout[i] = 0; g_cin[i] = 0; }
}

__global__ void k_deg(const int* __restrict__ src, const int* __restrict__ dst) {
    int e = blockIdx.x * blockDim.x + threadIdx.x;
    if (e < NE) {
        atomicAdd(&g_cout[src[e]], 1);
        atomicAdd(&g_cin[dst[e]], 1);
    }
}

__global__ __launch_bounds__(1024) void k_scan() {
    __shared__ int part[1024];
    int t = threadIdx.x;
    const int chunk = (NN + 1023) / 1024;
    int beg = t * chunk;
    int end = beg + chunk; if (end > NN) end = NN;
    int mysum = 0;
    for (int i = beg; i < end && i < NN; i++) mysum += g_cin[i];
    part[t] = mysum;
    __syncthreads();
    for (int d = 1; d < 1024; d <<= 1) {
        int v = (t >= d) ? part[t - d] : 0;
        __syncthreads();
        part[t] += v;
        __syncthreads();
    }
    int prefix = part[t] - mysum;
    for (int i = beg; i < end && i < NN; i++) {
        int c = g_cin[i];
        g_off[i] = prefix;
        g_cur[i] = prefix;
        prefix += c;
        int co = g_cout[i]; if (co < 1) co = 1;
        int ci = g_cin[i];  if (ci < 1) ci = 1;
        g_sout[i] = rsqrtf((float)co);
        g_sin[i]  = rsqrtf((float)ci);
    }
}

__global__ void k_scatter(const int* __restrict__ src, const int* __restrict__ dst) {
    int e = blockIdx.x * blockDim.x + threadIdx.x;
    if (e < NE) {
        int p = atomicAdd(&g_cur[dst[e]], 1);
        g_esrc[p] = src[e];
    }
}

// ---------------- GEMM1: P = feat @ W1  (10000 x 512 x 64) ----------------
__global__ __launch_bounds__(256) void k_gemm1(const float* __restrict__ feat,
                                               const float* __restrict__ W1) {
    __shared__ float sA[64][68];
    __shared__ float sB[64][64];
    int tid = threadIdx.x;
    int tx = tid & 15, ty = tid >> 4;
    int rowBase = blockIdx.x * 64;
    float acc[4][4] = {};
    for (int kt = 0; kt < FIN; kt += 64) {
#pragma unroll
        for (int it = 0; it < 4; it++) {
            int r = ty + it * 16;
            int gr = rowBase + r;
            float4 v = make_float4(0.f, 0.f, 0.f, 0.f);
            if (gr < NN) v = *(const float4*)(feat + (size_t)gr * FIN + kt + tx * 4);
            *(float4*)&sA[r][tx * 4] = v;
            *(float4*)&sB[r][tx * 4] = *(const float4*)(W1 + (size_t)(kt + r) * F + tx * 4);
        }
        __syncthreads();
#pragma unroll 16
        for (int kk = 0; kk < 64; kk++) {
            float a0 = sA[ty * 4 + 0][kk];
            float a1 = sA[ty * 4 + 1][kk];
            float a2 = sA[ty * 4 + 2][kk];
            float a3 = sA[ty * 4 + 3][kk];
            float4 b = *(float4*)&sB[kk][tx * 4];
            acc[0][0] += a0 * b.x; acc[0][1] += a0 * b.y; acc[0][2] += a0 * b.z; acc[0][3] += a0 * b.w;
            acc[1][0] += a1 * b.x; acc[1][1] += a1 * b.y; acc[1][2] += a1 * b.z; acc[1][3] += a1 * b.w;
            acc[2][0] += a2 * b.x; acc[2][1] += a2 * b.y; acc[2][2] += a2 * b.z; acc[2][3] += a2 * b.w;
            acc[3][0] += a3 * b.x; acc[3][1] += a3 * b.y; acc[3][2] += a3 * b.z; acc[3][3] += a3 * b.w;
        }
        __syncthreads();
    }
#pragma unroll
    for (int i = 0; i < 4; i++) {
        int r = rowBase + ty * 4 + i;
        if (r < NN) {
            float4 v = make_float4(acc[i][0], acc[i][1], acc[i][2], acc[i][3]);
            *(float4*)&g_P[r * F + tx * 4] = v;
        }
    }
}

// ---------------- gather 1 --------------------------------------------------
__global__ __launch_bounds__(256) void k_gather1(const float* __restrict__ b1) {
    int node = blockIdx.x * 8 + (threadIdx.x >> 5);
    if (node >= NN) return;
    int lane = threadIdx.x & 31;
    int beg = g_off[node];
    int cnt = g_cin[node];
    float a0 = 0.f, a1 = 0.f;
    int j = 0;
    for (; j + 4 <= cnt; j += 4) {
        int s0 = g_esrc[beg + j + 0];
        int s1 = g_esrc[beg + j + 1];
        int s2 = g_esrc[beg + j + 2];
        int s3 = g_esrc[beg + j + 3];
        float w0 = g_sout[s0], w1 = g_sout[s1], w2 = g_sout[s2], w3 = g_sout[s3];
        a0 += w0 * g_P[s0 * F + lane];      a1 += w0 * g_P[s0 * F + 32 + lane];
        a0 += w1 * g_P[s1 * F + lane];      a1 += w1 * g_P[s1 * F + 32 + lane];
        a0 += w2 * g_P[s2 * F + lane];      a1 += w2 * g_P[s2 * F + 32 + lane];
        a0 += w3 * g_P[s3 * F + lane];      a1 += w3 * g_P[s3 * F + 32 + lane];
    }
    for (; j < cnt; j++) {
        int s = g_esrc[beg + j];
        float w = g_sout[s];
        a0 += w * g_P[s * F + lane];
        a1 += w * g_P[s * F + 32 + lane];
    }
    float si = g_sin[node];
    float h0 = a0 * si + b1[lane];
    float h1 = a1 * si + b1[lane + 32];
    float so = g_sout[node];
    g_h1n[node * F + lane]       = h0 * so;
    g_h1n[node * F + 32 + lane]  = h1 * so;
}

// ---------------- GEMM2: hms = h1n @ [Wmu | Wstd] ---------------------------
__global__ __launch_bounds__(256) void k_gemm2(const float* __restrict__ Wmu,
                                               const float* __restrict__ Wstd) {
    __shared__ float sA[64][64];
    __shared__ float sW[64][128];
    int tid = threadIdx.x;
    int tx = tid & 15, ty = tid >> 4;
    int rowBase = blockIdx.x * 64;
    {
        int f4c = tid & 31;
        int k0 = tid >> 5;
#pragma unroll
        for (int it = 0; it < 8; it++) {
            int k = k0 + it * 8;
            float4 w;
            if (f4c < 16) w = *(const float4*)(Wmu + k * F + f4c * 4);
            else          w = *(const float4*)(Wstd + k * F + (f4c - 16) * 4);
            *(float4*)&sW[k][f4c * 4] = w;
        }
    }
#pragma unroll
    for (int it = 0; it < 4; it++) {
        int r = ty + it * 16;
        int gr = rowBase + r;
        float4 v = make_float4(0.f, 0.f, 0.f, 0.f);
        if (gr < NN) v = *(const float4*)&g_h1n[gr * F + tx * 4];
        *(float4*)&sA[r][tx * 4] = v;
    }
    __syncthreads();
    float acc[4][8] = {};
#pragma unroll 8
    for (int kk = 0; kk < 64; kk++) {
        float a0 = sA[ty * 4 + 0][kk];
        float a1 = sA[ty * 4 + 1][kk];
        float a2 = sA[ty * 4 + 2][kk];
        float a3 = sA[ty * 4 + 3][kk];
        float4 b0 = *(float4*)&sW[kk][tx * 8];
        float4 b1 = *(float4*)&sW[kk][tx * 8 + 4];
        acc[0][0] += a0 * b0.x; acc[0][1] += a0 * b0.y; acc[0][2] += a0 * b0.z; acc[0][3] += a0 * b0.w;
        acc[0][4] += a0 * b1.x; acc[0][5] += a0 * b1.y; acc[0][6] += a0 * b1.z; acc[0][7] += a0 * b1.w;
        acc[1][0] += a1 * b0.x; acc[1][1] += a1 * b0.y; acc[1][2] += a1 * b0.z; acc[1][3] += a1 * b0.w;
        acc[1][4] += a1 * b1.x; acc[1][5] += a1 * b1.y; acc[1][6] += a1 * b1.z; acc[1][7] += a1 * b1.w;
        acc[2][0] += a2 * b0.x; acc[2][1] += a2 * b0.y; acc[2][2] += a2 * b0.z; acc[2][3] += a2 * b0.w;
        acc[2][4] += a2 * b1.x; acc[2][5] += a2 * b1.y; acc[2][6] += a2 * b1.z; acc[2][7] += a2 * b1.w;
        acc[3][0] += a3 * b0.x; acc[3][1] += a3 * b0.y; acc[3][2] += a3 * b0.z; acc[3][3] += a3 * b0.w;
        acc[3][4] += a3 * b1.x; acc[3][5] += a3 * b1.y; acc[3][6] += a3 * b1.z; acc[3][7] += a3 * b1.w;
    }
#pragma unroll
    for (int i = 0; i < 4; i++) {
        int r = rowBase + ty * 4 + i;
        if (r < NN) {
            *(float4*)&g_hms[r * 128 + tx * 8]     = make_float4(acc[i][0], acc[i][1], acc[i][2], acc[i][3]);
            *(float4*)&g_hms[r * 128 + tx * 8 + 4] = make_float4(acc[i][4], acc[i][5], acc[i][6], acc[i][7]);
        }
    }
}

// ---------------- gather 2: mu/std/z + bf16 split --------------------------
__global__ __launch_bounds__(256) void k_gather2(const float* __restrict__ eps,
                                                 const float* __restrict__ bmu,
                                                 const float* __restrict__ bstd,
                                                 float* __restrict__ out) {
    int node = blockIdx.x * 8 + (threadIdx.x >> 5);
    if (node >= NN) return;
    int lane = threadIdx.x & 31;
    int beg = g_off[node];
    int cnt = g_cin[node];
    float m0 = 0.f, m1 = 0.f, v0 = 0.f, v1 = 0.f;
    int j = 0;
    for (; j + 2 <= cnt; j += 2) {
        int s0 = g_esrc[beg + j];
        int s1 = g_esrc[beg + j + 1];
        const float* p0 = &g_hms[s0 * 128];
        const float* p1 = &g_hms[s1 * 128];
        m0 += p0[lane];       m1 += p0[32 + lane];
        v0 += p0[64 + lane];  v1 += p0[96 + lane];
        m0 += p1[lane];       m1 += p1[32 + lane];
        v0 += p1[64 + lane];  v1 += p1[96 + lane];
    }
    for (; j < cnt; j++) {
        int s = g_esrc[beg + j];
        const float* p = &g_hms[s * 128];
        m0 += p[lane];       m1 += p[32 + lane];
        v0 += p[64 + lane];  v1 += p[96 + lane];
    }
    float si = g_sin[node];
    float mu0 = m0 * si + bmu[lane];
    float mu1 = m1 * si + bmu[lane + 32];
    float st0 = __expf(v0 * si + bstd[lane]);
    float st1 = __expf(v1 * si + bstd[lane + 32]);
    out[MU_OFF + (size_t)node * F + lane]       = mu0;
    out[MU_OFF + (size_t)node * F + 32 + lane]  = mu1;
    out[STD_OFF + (size_t)node * F + lane]      = st0;
    out[STD_OFF + (size_t)node * F + 32 + lane] = st1;
    float z0 = eps[node * F + lane]      * st0 + mu0;
    float z1 = eps[node * F + 32 + lane] * st1 + mu1;

    // bf16 split: z = h + l;  ZA=[h|l|h], ZB=[h|h|l] so ZA·ZB^T = hh + lh + hl
    __nv_bfloat16 h0 = __float2bfloat16_rn(z0);
    __nv_bfloat16 h1 = __float2bfloat16_rn(z1);
    __nv_bfloat16 l0 = __float2bfloat16_rn(z0 - __bfloat162float(h0));
    __nv_bfloat16 l1 = __float2bfloat16_rn(z1 - __bfloat162float(h1));
    __nv_bfloat16* za = &g_ZA[(size_t)node * 192];
    __nv_bfloat16* zb = &g_ZB[(size_t)node * 192];
    za[lane] = h0;       za[lane + 32] = h1;
    za[64 + lane] = l0;  za[96 + lane] = l1;
    za[128 + lane] = h0; za[160 + lane] = h1;
    zb[lane] = h0;       zb[lane + 32] = h1;
    zb[64 + lane] = h0;  zb[96 + lane] = h1;
    zb[128 + lane] = l0; zb[160 + lane] = l1;
}

// ---------------- adj = sigmoid(Z Z^T) via mma.sync bf16 --------------------
// CTA tile 128x128, warp tile 32x64 (4 M-warps x 2 N-warps), K=192 resident.
#define KW     192
#define STRD   200                       // bf16 row stride (400 B) - conflict-free ldmatrix
#define TILE_BYTES (128 * STRD * 2)      // 51200 B
#define ADJ_SMEM   (2 * TILE_BYTES)      // 102400 B
#define COL_TILES  79                    // ceil(10000/128)
#define QUARTERS   4

__global__ __launch_bounds__(256, 2) void k_adj_hmma(float* __restrict__ out) {
    extern __shared__ char smem[];
    char* smA = smem;
    char* smB = smem + TILE_BYTES;
    uint32_t sbA = smem_u32(smA);
    uint32_t sbB = smem_u32(smB);

    int tid = threadIdx.x;
    int wid = tid >> 5, lane = tid & 31;
    int wm = wid & 3;        // 0..3 : 32-row slice
    int wn = wid >> 2;       // 0..1 : 64-col slice

    int panel = blockIdx.x >> 2;           // 0..78
    int q = blockIdx.x & 3;
    int rb = panel * 128;
    int ct0 = q * 20;
    int ct1 = ct0 + 20; if (ct1 > COL_TILES) ct1 = COL_TILES;

    const char* ZA = (const char*)g_ZA;
    const char* ZB = (const char*)g_ZB;

    // load A panel (128 x 192 bf16) once
    for (int idx = tid; idx < 3072; idx += 256) {
        int r = idx / 24;
        int c = idx - r * 24;
        int grow = rb + r;
        uint4 v = make_uint4(0u, 0u, 0u, 0u);
        if (grow < NN) v = *(const uint4*)(ZA + (size_t)grow * 384 + c * 16);
        *(uint4*)(smA + r * (STRD * 2) + c * 16) = v;
    }

    // ldmatrix lane addressing (shared by A and B)
    int lrow = lane & 15;
    int lkh  = (lane >> 4) * 16;   // byte offset for k-half (8 bf16 = 16 B)

    for (int ctile = ct0; ctile < ct1; ctile++) {
        int cb = ctile * 128;
        __syncthreads();   // everyone done reading smB from previous iter
        for (int idx = tid; idx < 3072; idx += 256) {
            int r = idx / 24;
            int c = idx - r * 24;
            int grow = cb + r;
            uint4 v = make_uint4(0u, 0u, 0u, 0u);
            if (grow < NN) v = *(const uint4*)(ZB + (size_t)grow * 384 + c * 16);
            *(uint4*)(smB + r * (STRD * 2) + c * 16) = v;
        }
        __syncthreads();

        float acc[2][8][4];
#pragma unroll
        for (int mt = 0; mt < 2; mt++)
#pragma unroll
            for (int nt = 0; nt < 8; nt++)
#pragma unroll
                for (int u = 0; u < 4; u++) acc[mt][nt][u] = 0.f;

#pragma unroll
        for (int ks = 0; ks < KW / 16; ks++) {
            int kb = ks * 32;  // byte offset of k0 (16 bf16)
            uint32_t a[2][4];
#pragma unroll
            for (int mt = 0; mt < 2; mt++) {
                uint32_t addr = sbA + (wm * 32 + mt * 16 + lrow) * (STRD * 2) + kb + lkh;
                ldsm4(a[mt], addr);
            }
            uint32_t b[8][2];
#pragma unroll
            for (int bt = 0; bt < 4; bt++) {
                uint32_t tmp[4];
                uint32_t addr = sbB + (wn * 64 + bt * 16 + lrow) * (STRD * 2) + kb + lkh;
                ldsm4(tmp, addr);
                b[2 * bt][0] = tmp[0];     b[2 * bt][1] = tmp[2];
                b[2 * bt + 1][0] = tmp[1]; b[2 * bt + 1][1] = tmp[3];
            }
#pragma unroll
            for (int mt = 0; mt < 2; mt++)
#pragma unroll
                for (int nt = 0; nt < 8; nt++)
                    mma16816(acc[mt][nt], a[mt], b[nt]);
        }

        // epilogue: sigmoid + store (float2 per mma frag row)
        int group = lane >> 2;
        int qp = lane & 3;
#pragma unroll
        for (int mt = 0; mt < 2; mt++) {
            int r0 = rb + wm * 32 + mt * 16 + group;
            int r1 = r0 + 8;
            bool ok0 = r0 < NN, ok1 = r1 < NN;
            size_t ro0 = (size_t)r0 * NN, ro1 = (size_t)r1 * NN;
#pragma unroll
            for (int nt = 0; nt < 8; nt++) {
                int col = cb + wn * 64 + nt * 8 + qp * 2;
                if (col < NN) {
                    if (ok0) {
                        float2 v = make_float2(sigf(acc[mt][nt][0]), sigf(acc[mt][nt][1]));
                        *(float2*)(out + ro0 + col) = v;
                    }
                    if (ok1) {
                        float2 v = make_float2(sigf(acc[mt][nt][2]), sigf(acc[mt][nt][3]));
                        *(float2*)(out + ro1 + col) = v;
                    }
                }
            }
        }
    }
}

// ---------------- launcher -------------------------------------------------
extern "C" void kernel_launch(void* const* d_in, const int* in_sizes, int n_in,
                              void* d_out, int out_size) {
    (void)in_sizes; (void)n_in; (void)out_size;
    const float* feat = (const float*)d_in[0];
    const float* eps  = (const float*)d_in[1];
    const int*   src  = (const int*)d_in[2];
    const int*   dst  = (const int*)d_in[3];
    const float* W1   = (const float*)d_in[4];
    const float* b1   = (const float*)d_in[5];
    const float* Wmu  = (const float*)d_in[6];
    const float* bmu  = (const float*)d_in[7];
    const float* Wstd = (const float*)d_in[8];
    const float* bstd = (const float*)d_in[9];
    float* out = (float*)d_out;

    static bool init = false;
    if (!init) {
        cudaFuncSetAttribute(k_adj_hmma, cudaFuncAttributeMaxDynamicSharedMemorySize, ADJ_SMEM);
        init = true;
    }

    k_zero<<<(NN + 255) / 256, 256>>>();
    k_deg<<<NE / 256, 256>>>(src, dst);
    k_scan<<<1, 1024>>>();
    k_scatter<<<NE / 256, 256>>>(src, dst);
    k_gemm1<<<(NN + 63) / 64, 256>>>(feat, W1);
    k_gather1<<<(NN + 7) / 8, 256>>>(b1);
    k_gemm2<<<(NN + 63) / 64, 256>>>(Wmu, Wstd);
    k_gather2<<<(NN + 7) / 8, 256>>>(eps, bmu, bstd, out);
    k_adj_hmma<<<COL_TILES * QUARTERS, 256, ADJ_SMEM>>>(out);
}

// round 4
// speedup vs baseline: 1.6021x; 1.5376x over previous
#include <cuda_runtime.h>
#include <cuda_bf16.h>
#include <cstdint>

#define NN   10000
#define NE   320000
#define FIN  512
#define F    64

#define MU_OFF  ((size_t)NN * (size_t)NN)
#define STD_OFF (MU_OFF + (size_t)NN * F)

// ---------------- scratch (device globals; no allocation allowed) ----------
__device__ float g_P[NN * F];
__device__ float g_h1n[NN * F];
__device__ float g_hms[NN * 2 * F];
__device__ __nv_bfloat16 g_ZA[NN * 192];  // [h | l | h]
__device__ __nv_bfloat16 g_ZB[NN * 192];  // [h | h | l]
__device__ float g_sout[NN];
__device__ float g_sin[NN];
__device__ int   g_cout[NN];
__device__ int   g_cin[NN];
__device__ int   g_off[NN];
__device__ int   g_cur[NN];
__device__ int   g_esrc[NE];

// ---------------- helpers ----------------------------------------------------
__device__ __forceinline__ uint32_t smem_u32(const void* p) {
    uint32_t a;
    asm("{ .reg .u64 t; cvta.to.shared.u64 t, %1; cvt.u32.u64 %0, t; }" : "=r"(a) : "l"(p));
    return a;
}
__device__ __forceinline__ void ldsm4(uint32_t* r, uint32_t addr) {
    asm volatile("ldmatrix.sync.aligned.m8n8.x4.shared.b16 {%0,%1,%2,%3}, [%4];"
        : "=r"(r[0]), "=r"(r[1]), "=r"(r[2]), "=r"(r[3]) : "r"(addr));
}
__device__ __forceinline__ void mma16816(float* d, const uint32_t* a, const uint32_t* b) {
    asm volatile("mma.sync.aligned.m16n8k16.row.col.f32.bf16.bf16.f32 "
        "{%0,%1,%2,%3},{%4,%5,%6,%7},{%8,%9},{%0,%1,%2,%3};"
        : "+f"(d[0]), "+f"(d[1]), "+f"(d[2]), "+f"(d[3])
        : "r"(a[0]), "r"(a[1]), "r"(a[2]), "r"(a[3]), "r"(b[0]), "r"(b[1]));
}
__device__ __forceinline__ float sigf(float x) {
    return __fdividef(1.0f, 1.0f + __expf(-x));
}

// ---------------- graph preprocessing -------------------------------------
__global__ void k_zero() {
    int i = blockIdx.x * blockDim.x + threadIdx.x;
    if (i < NN) { g_cout[i] = 0; g_cin[i] = 0; }
}

__global__ void k_deg(const int* __restrict__ src, const int* __restrict__ dst) {
    int e = blockIdx.x * blockDim.x + threadIdx.x;
    if (e < NE) {
        atomicAdd(&g_cout[src[e]], 1);
        atomicAdd(&g_cin[dst[e]], 1);
    }
}

__global__ __launch_bounds__(1024) void k_scan() {
    __shared__ int part[1024];
    int t = threadIdx.x;
    const int chunk = (NN + 1023) / 1024;
    int beg = t * chunk;
    int end = beg + chunk; if (end > NN) end = NN;
    int mysum = 0;
    for (int i = beg; i < end && i < NN; i++) mysum += g_cin[i];
    part[t] = mysum;
    __syncthreads();
    for (int d = 1; d < 1024; d <<= 1) {
        int v = (t >= d) ? part[t - d] : 0;
        __syncthreads();
        part[t] += v;
        __syncthreads();
    }
    int prefix = part[t] - mysum;
    for (int i = beg; i < end && i < NN; i++) {
        int c = g_cin[i];
        g_off[i] = prefix;
        g_cur[i] = prefix;
        prefix += c;
        int co = g_cout[i]; if (co < 1) co = 1;
        int ci = g_cin[i];  if (ci < 1) ci = 1;
        g_sout[i] = rsqrtf((float)co);
        g_sin[i]  = rsqrtf((float)ci);
    }
}

__global__ void k_scatter(const int* __restrict__ src, const int* __restrict__ dst) {
    int e = blockIdx.x * blockDim.x + threadIdx.x;
    if (e < NE) {
        int p = atomicAdd(&g_cur[dst[e]], 1);
        g_esrc[p] = src[e];
    }
}

// ---------------- GEMM1: P = feat @ W1  (10000 x 512 x 64) ----------------
__global__ __launch_bounds__(256) void k_gemm1(const float* __restrict__ feat,
                                               const float* __restrict__ W1) {
    __shared__ float sA[64][68];
    __shared__ float sB[64][64];
    int tid = threadIdx.x;
    int tx = tid & 15, ty = tid >> 4;
    int rowBase = blockIdx.x * 64;
    float acc[4][4] = {};
    for (int kt = 0; kt < FIN; kt += 64) {
#pragma unroll
        for (int it = 0; it < 4; it++) {
            int r = ty + it * 16;
            int gr = rowBase + r;
            float4 v = make_float4(0.f, 0.f, 0.f, 0.f);
            if (gr < NN) v = *(const float4*)(feat + (size_t)gr * FIN + kt + tx * 4);
            *(float4*)&sA[r][tx * 4] = v;
            *(float4*)&sB[r][tx * 4] = *(const float4*)(W1 + (size_t)(kt + r) * F + tx * 4);
        }
        __syncthreads();
#pragma unroll 16
        for (int kk = 0; kk < 64; kk++) {
            float a0 = sA[ty * 4 + 0][kk];
            float a1 = sA[ty * 4 + 1][kk];
            float a2 = sA[ty * 4 + 2][kk];
            float a3 = sA[ty * 4 + 3][kk];
            float4 b = *(float4*)&sB[kk][tx * 4];
            acc[0][0] += a0 * b.x; acc[0][1] += a0 * b.y; acc[0][2] += a0 * b.z; acc[0][3] += a0 * b.w;
            acc[1][0] += a1 * b.x; acc[1][1] += a1 * b.y; acc[1][2] += a1 * b.z; acc[1][3] += a1 * b.w;
            acc[2][0] += a2 * b.x; acc[2][1] += a2 * b.y; acc[2][2] += a2 * b.z; acc[2][3] += a2 * b.w;
            acc[3][0] += a3 * b.x; acc[3][1] += a3 * b.y; acc[3][2] += a3 * b.z; acc[3][3] += a3 * b.w;
        }
        __syncthreads();
    }
#pragma unroll
    for (int i = 0; i < 4; i++) {
        int r = rowBase + ty * 4 + i;
        if (r < NN) {
            float4 v = make_float4(acc[i][0], acc[i][1], acc[i][2], acc[i][3]);
            *(float4*)&g_P[r * F + tx * 4] = v;
        }
    }
}

// ---------------- gather 1 --------------------------------------------------
__global__ __launch_bounds__(256) void k_gather1(const float* __restrict__ b1) {
    int node = blockIdx.x * 8 + (threadIdx.x >> 5);
    if (node >= NN) return;
    int lane = threadIdx.x & 31;
    int beg = g_off[node];
    int cnt = g_cin[node];
    float a0 = 0.f, a1 = 0.f;
    int j = 0;
    for (; j + 4 <= cnt; j += 4) {
        int s0 = g_esrc[beg + j + 0];
        int s1 = g_esrc[beg + j + 1];
        int s2 = g_esrc[beg + j + 2];
        int s3 = g_esrc[beg + j + 3];
        float w0 = g_sout[s0], w1 = g_sout[s1], w2 = g_sout[s2], w3 = g_sout[s3];
        a0 += w0 * g_P[s0 * F + lane];      a1 += w0 * g_P[s0 * F + 32 + lane];
        a0 += w1 * g_P[s1 * F + lane];      a1 += w1 * g_P[s1 * F + 32 + lane];
        a0 += w2 * g_P[s2 * F + lane];      a1 += w2 * g_P[s2 * F + 32 + lane];
        a0 += w3 * g_P[s3 * F + lane];      a1 += w3 * g_P[s3 * F + 32 + lane];
    }
    for (; j < cnt; j++) {
        int s = g_esrc[beg + j];
        float w = g_sout[s];
        a0 += w * g_P[s * F + lane];
        a1 += w * g_P[s * F + 32 + lane];
    }
    float si = g_sin[node];
    float h0 = a0 * si + b1[lane];
    float h1 = a1 * si + b1[lane + 32];
    float so = g_sout[node];
    g_h1n[node * F + lane]       = h0 * so;
    g_h1n[node * F + 32 + lane]  = h1 * so;
}

// ---------------- GEMM2: hms = h1n @ [Wmu | Wstd] ---------------------------
__global__ __launch_bounds__(256) void k_gemm2(const float* __restrict__ Wmu,
                                               const float* __restrict__ Wstd) {
    __shared__ float sA[64][64];
    __shared__ float sW[64][128];
    int tid = threadIdx.x;
    int tx = tid & 15, ty = tid >> 4;
    int rowBase = blockIdx.x * 64;
    {
        int f4c = tid & 31;
        int k0 = tid >> 5;
#pragma unroll
        for (int it = 0; it < 8; it++) {
            int k = k0 + it * 8;
            float4 w;
            if (f4c < 16) w = *(const float4*)(Wmu + k * F + f4c * 4);
            else          w = *(const float4*)(Wstd + k * F + (f4c - 16) * 4);
            *(float4*)&sW[k][f4c * 4] = w;
        }
    }
#pragma unroll
    for (int it = 0; it < 4; it++) {
        int r = ty + it * 16;
        int gr = rowBase + r;
        float4 v = make_float4(0.f, 0.f, 0.f, 0.f);
        if (gr < NN) v = *(const float4*)&g_h1n[gr * F + tx * 4];
        *(float4*)&sA[r][tx * 4] = v;
    }
    __syncthreads();
    float acc[4][8] = {};
#pragma unroll 8
    for (int kk = 0; kk < 64; kk++) {
        float a0 = sA[ty * 4 + 0][kk];
        float a1 = sA[ty * 4 + 1][kk];
        float a2 = sA[ty * 4 + 2][kk];
        float a3 = sA[ty * 4 + 3][kk];
        float4 b0 = *(float4*)&sW[kk][tx * 8];
        float4 b1 = *(float4*)&sW[kk][tx * 8 + 4];
        acc[0][0] += a0 * b0.x; acc[0][1] += a0 * b0.y; acc[0][2] += a0 * b0.z; acc[0][3] += a0 * b0.w;
        acc[0][4] += a0 * b1.x; acc[0][5] += a0 * b1.y; acc[0][6] += a0 * b1.z; acc[0][7] += a0 * b1.w;
        acc[1][0] += a1 * b0.x; acc[1][1] += a1 * b0.y; acc[1][2] += a1 * b0.z; acc[1][3] += a1 * b0.w;
        acc[1][4] += a1 * b1.x; acc[1][5] += a1 * b1.y; acc[1][6] += a1 * b1.z; acc[1][7] += a1 * b1.w;
        acc[2][0] += a2 * b0.x; acc[2][1] += a2 * b0.y; acc[2][2] += a2 * b0.z; acc[2][3] += a2 * b0.w;
        acc[2][4] += a2 * b1.x; acc[2][5] += a2 * b1.y; acc[2][6] += a2 * b1.z; acc[2][7] += a2 * b1.w;
        acc[3][0] += a3 * b0.x; acc[3][1] += a3 * b0.y; acc[3][2] += a3 * b0.z; acc[3][3] += a3 * b0.w;
        acc[3][4] += a3 * b1.x; acc[3][5] += a3 * b1.y; acc[3][6] += a3 * b1.z; acc[3][7] += a3 * b1.w;
    }
#pragma unroll
    for (int i = 0; i < 4; i++) {
        int r = rowBase + ty * 4 + i;
        if (r < NN) {
            *(float4*)&g_hms[r * 128 + tx * 8]     = make_float4(acc[i][0], acc[i][1], acc[i][2], acc[i][3]);
            *(float4*)&g_hms[r * 128 + tx * 8 + 4] = make_float4(acc[i][4], acc[i][5], acc[i][6], acc[i][7]);
        }
    }
}

// ---------------- gather 2: mu/std/z + bf16 split --------------------------
__global__ __launch_bounds__(256) void k_gather2(const float* __restrict__ eps,
                                                 const float* __restrict__ bmu,
                                                 const float* __restrict__ bstd,
                                                 float* __restrict__ out) {
    int node = blockIdx.x * 8 + (threadIdx.x >> 5);
    if (node >= NN) return;
    int lane = threadIdx.x & 31;
    int beg = g_off[node];
    int cnt = g_cin[node];
    float m0 = 0.f, m1 = 0.f, v0 = 0.f, v1 = 0.f;
    int j = 0;
    for (; j + 2 <= cnt; j += 2) {
        int s0 = g_esrc[beg + j];
        int s1 = g_esrc[beg + j + 1];
        const float* p0 = &g_hms[s0 * 128];
        const float* p1 = &g_hms[s1 * 128];
        m0 += p0[lane];       m1 += p0[32 + lane];
        v0 += p0[64 + lane];  v1 += p0[96 + lane];
        m0 += p1[lane];       m1 += p1[32 + lane];
        v0 += p1[64 + lane];  v1 += p1[96 + lane];
    }
    for (; j < cnt; j++) {
        int s = g_esrc[beg + j];
        const float* p = &g_hms[s * 128];
        m0 += p[lane];       m1 += p[32 + lane];
        v0 += p[64 + lane];  v1 += p[96 + lane];
    }
    float si = g_sin[node];
    float mu0 = m0 * si + bmu[lane];
    float mu1 = m1 * si + bmu[lane + 32];
    float st0 = __expf(v0 * si + bstd[lane]);
    float st1 = __expf(v1 * si + bstd[lane + 32]);
    out[MU_OFF + (size_t)node * F + lane]       = mu0;
    out[MU_OFF + (size_t)node * F + 32 + lane]  = mu1;
    out[STD_OFF + (size_t)node * F + lane]      = st0;
    out[STD_OFF + (size_t)node * F + 32 + lane] = st1;
    float z0 = eps[node * F + lane]      * st0 + mu0;
    float z1 = eps[node * F + 32 + lane] * st1 + mu1;

    __nv_bfloat16 h0 = __float2bfloat16_rn(z0);
    __nv_bfloat16 h1 = __float2bfloat16_rn(z1);
    __nv_bfloat16 l0 = __float2bfloat16_rn(z0 - __bfloat162float(h0));
    __nv_bfloat16 l1 = __float2bfloat16_rn(z1 - __bfloat162float(h1));
    __nv_bfloat16* za = &g_ZA[(size_t)node * 192];
    __nv_bfloat16* zb = &g_ZB[(size_t)node * 192];
    za[lane] = h0;       za[lane + 32] = h1;
    za[64 + lane] = l0;  za[96 + lane] = l1;
    za[128 + lane] = h0; za[160 + lane] = h1;
    zb[lane] = h0;       zb[lane + 32] = h1;
    zb[64 + lane] = h0;  zb[96 + lane] = h1;
    zb[128 + lane] = l0; zb[160 + lane] = l1;
}

// ---------------- adj = sigmoid(Z Z^T), symmetric, persistent ---------------
#define KW     192
#define STRD   200
#define TILE_BYTES (128 * STRD * 2)      // 51200 B
#define ADJ_SMEM   (2 * TILE_BYTES)      // 102400 B
#define NPAN   79                        // ceil(10000/128)
#define NT_UT  (NPAN * (NPAN + 1) / 2)   // 3160 upper-tri tiles
#define ADJ_GRID 296                     // 2 CTAs/SM x 148 SMs = 1 wave
#define ADJ_CHUNK ((NT_UT + ADJ_GRID - 1) / ADJ_GRID)  // 11

__global__ __launch_bounds__(256, 2) void k_adj_hmma(float* __restrict__ out) {
    extern __shared__ char smem[];
    char* smA = smem;
    char* smB = smem + TILE_BYTES;
    uint32_t sbA = smem_u32(smA);
    uint32_t sbB = smem_u32(smB);

    int tid = threadIdx.x;
    int wid = tid >> 5, lane = tid & 31;
    int wm = wid & 3;
    int wn = wid >> 2;
    int group = lane >> 2;
    int qp = lane & 3;
    int lrow = lane & 15;
    int lkh  = (lane >> 4) * 16;

    int t0 = blockIdx.x * ADJ_CHUNK;
    int t1 = t0 + ADJ_CHUNK; if (t1 > NT_UT) t1 = NT_UT;
    if (t0 >= NT_UT) return;

    // locate starting (p, c) in the upper-triangular enumeration
    int p = 0, base = 0;
    while (base + (NPAN - p) <= t0) { base += NPAN - p; p++; }
    int c = p + (t0 - base);

    const char* ZA = (const char*)g_ZA;
    const char* ZB = (const char*)g_ZB;
    int curp = -1;

    for (int t = t0; t < t1; t++) {
        if (c >= NPAN) { p++; c = p; }
        int rb = p * 128, cb = c * 128;

        __syncthreads();   // all warps done reading smem from previous tile
        if (p != curp) {
            for (int idx = tid; idx < 3072; idx += 256) {
                int r = idx / 24;
                int cc = idx - r * 24;
                int grow = rb + r;
                uint4 v = make_uint4(0u, 0u, 0u, 0u);
                if (grow < NN) v = *(const uint4*)(ZA + (size_t)grow * 384 + cc * 16);
                *(uint4*)(smA + r * (STRD * 2) + cc * 16) = v;
            }
            curp = p;
        }
        for (int idx = tid; idx < 3072; idx += 256) {
            int r = idx / 24;
            int cc = idx - r * 24;
            int grow = cb + r;
            uint4 v = make_uint4(0u, 0u, 0u, 0u);
            if (grow < NN) v = *(const uint4*)(ZB + (size_t)grow * 384 + cc * 16);
            *(uint4*)(smB + r * (STRD * 2) + cc * 16) = v;
        }
        __syncthreads();

        float acc[2][8][4];
#pragma unroll
        for (int mt = 0; mt < 2; mt++)
#pragma unroll
            for (int nt = 0; nt < 8; nt++)
#pragma unroll
                for (int u = 0; u < 4; u++) acc[mt][nt][u] = 0.f;

#pragma unroll
        for (int ks = 0; ks < KW / 16; ks++) {
            int kb = ks * 32;
            uint32_t a[2][4];
#pragma unroll
            for (int mt = 0; mt < 2; mt++) {
                uint32_t addr = sbA + (wm * 32 + mt * 16 + lrow) * (STRD * 2) + kb + lkh;
                ldsm4(a[mt], addr);
            }
            uint32_t b[8][2];
#pragma unroll
            for (int bt = 0; bt < 4; bt++) {
                uint32_t tmp[4];
                uint32_t addr = sbB + (wn * 64 + bt * 16 + lrow) * (STRD * 2) + kb + lkh;
                ldsm4(tmp, addr);
                b[2 * bt][0] = tmp[0];     b[2 * bt][1] = tmp[2];
                b[2 * bt + 1][0] = tmp[1]; b[2 * bt + 1][1] = tmp[3];
            }
#pragma unroll
            for (int mt = 0; mt < 2; mt++)
#pragma unroll
                for (int nt = 0; nt < 8; nt++)
                    mma16816(acc[mt][nt], a[mt], b[nt]);
        }

        // sigmoid in place (computed once, stored twice)
#pragma unroll
        for (int mt = 0; mt < 2; mt++)
#pragma unroll
            for (int nt = 0; nt < 8; nt++)
#pragma unroll
                for (int u = 0; u < 4; u++) acc[mt][nt][u] = sigf(acc[mt][nt][u]);

        // direct store: block (rb, cb)
#pragma unroll
        for (int mt = 0; mt < 2; mt++) {
            int r0 = rb + wm * 32 + mt * 16 + group;
            int r1 = r0 + 8;
            bool ok0 = r0 < NN, ok1 = r1 < NN;
            size_t ro0 = (size_t)r0 * NN, ro1 = (size_t)r1 * NN;
#pragma unroll
            for (int nt = 0; nt < 8; nt++) {
                int col = cb + wn * 64 + nt * 8 + qp * 2;
                if (col < NN) {
                    if (ok0) *(float2*)(out + ro0 + col) = make_float2(acc[mt][nt][0], acc[mt][nt][1]);
                    if (ok1) *(float2*)(out + ro1 + col) = make_float2(acc[mt][nt][2], acc[mt][nt][3]);
                }
            }
        }
        // mirrored store: block (cb, rb), transposed
        if (p != c) {
#pragma unroll
            for (int mt = 0; mt < 2; mt++) {
                int r0 = rb + wm * 32 + mt * 16 + group;
                int r1 = r0 + 8;
                bool ok0 = r0 < NN, ok1 = r1 < NN;
#pragma unroll
                for (int nt = 0; nt < 8; nt++) {
                    int col = cb + wn * 64 + nt * 8 + qp * 2;
                    if (col < NN) {
                        if (ok0) out[(size_t)col * NN + r0] = acc[mt][nt][0];
                        if (ok1) out[(size_t)col * NN + r1] = acc[mt][nt][2];
                    }
                    if (col + 1 < NN) {
                        if (ok0) out[(size_t)(col + 1) * NN + r0] = acc[mt][nt][1];
                        if (ok1) out[(size_t)(col + 1) * NN + r1] = acc[mt][nt][3];
                    }
                }
            }
        }
        c++;
    }
}

// ---------------- launcher -------------------------------------------------
extern "C" void kernel_launch(void* const* d_in, const int* in_sizes, int n_in,
                              void* d_out, int out_size) {
    (void)in_sizes; (void)n_in; (void)out_size;
    const float* feat = (const float*)d_in[0];
    const float* eps  = (const float*)d_in[1];
    const int*   src  = (const int*)d_in[2];
    const int*   dst  = (const int*)d_in[3];
    const float* W1   = (const float*)d_in[4];
    const float* b1   = (const float*)d_in[5];
    const float* Wmu  = (const float*)d_in[6];
    const float* bmu  = (const float*)d_in[7];
    const float* Wstd = (const float*)d_in[8];
    const float* bstd = (const float*)d_in[9];
    float* out = (float*)d_out;

    static bool init = false;
    if (!init) {
        cudaFuncSetAttribute(k_adj_hmma, cudaFuncAttributeMaxDynamicSharedMemorySize, ADJ_SMEM);
        init = true;
    }

    k_zero<<<(NN + 255) / 256, 256>>>();
    k_deg<<<NE / 256, 256>>>(src, dst);
    k_scan<<<1, 1024>>>();
    k_scatter<<<NE / 256, 256>>>(src, dst);
    k_gemm1<<<(NN + 63) / 64, 256>>>(feat, W1);
    k_gather1<<<(NN + 7) / 8, 256>>>(b1);
    k_gemm2<<<(NN + 63) / 64, 256>>>(Wmu, Wstd);
    k_gather2<<<(NN + 7) / 8, 256>>>(eps, bmu, bstd, out);
    k_adj_hmma<<<ADJ_GRID, 256, ADJ_SMEM>>>(out);
}

// round 5
// speedup vs baseline: 1.6592x; 1.0357x over previous
#include <cuda_runtime.h>
#include <cuda_bf16.h>
#include <cstdint>

#define NN   10000
#define NE   320000
#define FIN  512
#define F    64

#define MU_OFF  ((size_t)NN * (size_t)NN)
#define STD_OFF (MU_OFF + (size_t)NN * F)

// ---------------- scratch (device globals; no allocation allowed) ----------
__device__ float g_P[NN * F];
__device__ float g_h1n[NN * F];
__device__ float g_hms[NN * 2 * F];
__device__ __nv_bfloat16 g_ZA[NN * 192];  // [h | l | h]
__device__ __nv_bfloat16 g_ZB[NN * 192];  // [h | h | l]
__device__ float g_sout[NN];
__device__ float g_sin[NN];
__device__ int   g_cout[NN];
__device__ int   g_cin[NN];
__device__ int   g_off[NN];
__device__ int   g_cur[NN];
__device__ int   g_esrc[NE];

// ---------------- helpers ----------------------------------------------------
__device__ __forceinline__ uint32_t smem_u32(const void* p) {
    uint32_t a;
    asm("{ .reg .u64 t; cvta.to.shared.u64 t, %1; cvt.u32.u64 %0, t; }" : "=r"(a) : "l"(p));
    return a;
}
__device__ __forceinline__ void ldsm4(uint32_t* r, uint32_t addr) {
    asm volatile("ldmatrix.sync.aligned.m8n8.x4.shared.b16 {%0,%1,%2,%3}, [%4];"
        : "=r"(r[0]), "=r"(r[1]), "=r"(r[2]), "=r"(r[3]) : "r"(addr));
}
__device__ __forceinline__ void mma16816(float* d, const uint32_t* a, const uint32_t* b) {
    asm volatile("mma.sync.aligned.m16n8k16.row.col.f32.bf16.bf16.f32 "
        "{%0,%1,%2,%3},{%4,%5,%6,%7},{%8,%9},{%0,%1,%2,%3};"
        : "+f"(d[0]), "+f"(d[1]), "+f"(d[2]), "+f"(d[3])
        : "r"(a[0]), "r"(a[1]), "r"(a[2]), "r"(a[3]), "r"(b[0]), "r"(b[1]));
}
__device__ __forceinline__ void cpasync16(uint32_t dst, const void* src, int srcsize) {
    asm volatile("cp.async.cg.shared.global [%0], [%1], 16, %2;"
        :: "r"(dst), "l"(src), "r"(srcsize) : "memory");
}
#define CP_COMMIT() asm volatile("cp.async.commit_group;" ::: "memory")
#define CP_WAIT0()  asm volatile("cp.async.wait_group 0;" ::: "memory")
__device__ __forceinline__ float sigf(float x) {
    return __fdividef(1.0f, 1.0f + __expf(-x));
}

// ---------------- graph preprocessing -------------------------------------
__global__ void k_zero() {
    int i = blockIdx.x * blockDim.x + threadIdx.x;
    if (i < NN) { g_cout[i] = 0; g_cin[i] = 0; }
}

__global__ void k_deg(const int* __restrict__ src, const int* __restrict__ dst) {
    int e = blockIdx.x * blockDim.x + threadIdx.x;
    if (e < NE) {
        atomicAdd(&g_cout[src[e]], 1);
        atomicAdd(&g_cin[dst[e]], 1);
    }
}

__global__ __launch_bounds__(1024) void k_scan() {
    __shared__ int part[1024];
    int t = threadIdx.x;
    const int chunk = (NN + 1023) / 1024;
    int beg = t * chunk;
    int end = beg + chunk; if (end > NN) end = NN;
    int mysum = 0;
    for (int i = beg; i < end && i < NN; i++) mysum += g_cin[i];
    part[t] = mysum;
    __syncthreads();
    for (int d = 1; d < 1024; d <<= 1) {
        int v = (t >= d) ? part[t - d] : 0;
        __syncthreads();
        part[t] += v;
        __syncthreads();
    }
    int prefix = part[t] - mysum;
    for (int i = beg; i < end && i < NN; i++) {
        int c = g_cin[i];
        g_off[i] = prefix;
        g_cur[i] = prefix;
        prefix += c;
        int co = g_cout[i]; if (co < 1) co = 1;
        int ci = g_cin[i];  if (ci < 1) ci = 1;
        g_sout[i] = rsqrtf((float)co);
        g_sin[i]  = rsqrtf((float)ci);
    }
}

__global__ void k_scatter(const int* __restrict__ src, const int* __restrict__ dst) {
    int e = blockIdx.x * blockDim.x + threadIdx.x;
    if (e < NE) {
        int p = atomicAdd(&g_cur[dst[e]], 1);
        g_esrc[p] = src[e];
    }
}

// ---------------- GEMM1: P = feat @ W1  (10000 x 512 x 64) ----------------
__global__ __launch_bounds__(256) void k_gemm1(const float* __restrict__ feat,
                                               const float* __restrict__ W1) {
    __shared__ float sA[64][68];
    __shared__ float sB[64][64];
    int tid = threadIdx.x;
    int tx = tid & 15, ty = tid >> 4;
    int rowBase = blockIdx.x * 64;
    float acc[4][4] = {};
    for (int kt = 0; kt < FIN; kt += 64) {
#pragma unroll
        for (int it = 0; it < 4; it++) {
            int r = ty + it * 16;
            int gr = rowBase + r;
            float4 v = make_float4(0.f, 0.f, 0.f, 0.f);
            if (gr < NN) v = *(const float4*)(feat + (size_t)gr * FIN + kt + tx * 4);
            *(float4*)&sA[r][tx * 4] = v;
            *(float4*)&sB[r][tx * 4] = *(const float4*)(W1 + (size_t)(kt + r) * F + tx * 4);
        }
        __syncthreads();
#pragma unroll 16
        for (int kk = 0; kk < 64; kk++) {
            float a0 = sA[ty * 4 + 0][kk];
            float a1 = sA[ty * 4 + 1][kk];
            float a2 = sA[ty * 4 + 2][kk];
            float a3 = sA[ty * 4 + 3][kk];
            float4 b = *(float4*)&sB[kk][tx * 4];
            acc[0][0] += a0 * b.x; acc[0][1] += a0 * b.y; acc[0][2] += a0 * b.z; acc[0][3] += a0 * b.w;
            acc[1][0] += a1 * b.x; acc[1][1] += a1 * b.y; acc[1][2] += a1 * b.z; acc[1][3] += a1 * b.w;
            acc[2][0] += a2 * b.x; acc[2][1] += a2 * b.y; acc[2][2] += a2 * b.z; acc[2][3] += a2 * b.w;
            acc[3][0] += a3 * b.x; acc[3][1] += a3 * b.y; acc[3][2] += a3 * b.z; acc[3][3] += a3 * b.w;
        }
        __syncthreads();
    }
#pragma unroll
    for (int i = 0; i < 4; i++) {
        int r = rowBase + ty * 4 + i;
        if (r < NN) {
            float4 v = make_float4(acc[i][0], acc[i][1], acc[i][2], acc[i][3]);
            *(float4*)&g_P[r * F + tx * 4] = v;
        }
    }
}

// ---------------- gather 1 --------------------------------------------------
__global__ __launch_bounds__(256) void k_gather1(const float* __restrict__ b1) {
    int node = blockIdx.x * 8 + (threadIdx.x >> 5);
    if (node >= NN) return;
    int lane = threadIdx.x & 31;
    int beg = g_off[node];
    int cnt = g_cin[node];
    float a0 = 0.f, a1 = 0.f;
    int j = 0;
    for (; j + 4 <= cnt; j += 4) {
        int s0 = g_esrc[beg + j + 0];
        int s1 = g_esrc[beg + j + 1];
        int s2 = g_esrc[beg + j + 2];
        int s3 = g_esrc[beg + j + 3];
        float w0 = g_sout[s0], w1 = g_sout[s1], w2 = g_sout[s2], w3 = g_sout[s3];
        a0 += w0 * g_P[s0 * F + lane];      a1 += w0 * g_P[s0 * F + 32 + lane];
        a0 += w1 * g_P[s1 * F + lane];      a1 += w1 * g_P[s1 * F + 32 + lane];
        a0 += w2 * g_P[s2 * F + lane];      a1 += w2 * g_P[s2 * F + 32 + lane];
        a0 += w3 * g_P[s3 * F + lane];      a1 += w3 * g_P[s3 * F + 32 + lane];
    }
    for (; j < cnt; j++) {
        int s = g_esrc[beg + j];
        float w = g_sout[s];
        a0 += w * g_P[s * F + lane];
        a1 += w * g_P[s * F + 32 + lane];
    }
    float si = g_sin[node];
    float h0 = a0 * si + b1[lane];
    float h1 = a1 * si + b1[lane + 32];
    float so = g_sout[node];
    g_h1n[node * F + lane]       = h0 * so;
    g_h1n[node * F + 32 + lane]  = h1 * so;
}

// ---------------- GEMM2: hms = h1n @ [Wmu | Wstd] ---------------------------
__global__ __launch_bounds__(256) void k_gemm2(const float* __restrict__ Wmu,
                                               const float* __restrict__ Wstd) {
    __shared__ float sA[64][64];
    __shared__ float sW[64][128];
    int tid = threadIdx.x;
    int tx = tid & 15, ty = tid >> 4;
    int rowBase = blockIdx.x * 64;
    {
        int f4c = tid & 31;
        int k0 = tid >> 5;
#pragma unroll
        for (int it = 0; it < 8; it++) {
            int k = k0 + it * 8;
            float4 w;
            if (f4c < 16) w = *(const float4*)(Wmu + k * F + f4c * 4);
            else          w = *(const float4*)(Wstd + k * F + (f4c - 16) * 4);
            *(float4*)&sW[k][f4c * 4] = w;
        }
    }
#pragma unroll
    for (int it = 0; it < 4; it++) {
        int r = ty + it * 16;
        int gr = rowBase + r;
        float4 v = make_float4(0.f, 0.f, 0.f, 0.f);
        if (gr < NN) v = *(const float4*)&g_h1n[gr * F + tx * 4];
        *(float4*)&sA[r][tx * 4] = v;
    }
    __syncthreads();
    float acc[4][8] = {};
#pragma unroll 8
    for (int kk = 0; kk < 64; kk++) {
        float a0 = sA[ty * 4 + 0][kk];
        float a1 = sA[ty * 4 + 1][kk];
        float a2 = sA[ty * 4 + 2][kk];
        float a3 = sA[ty * 4 + 3][kk];
        float4 b0 = *(float4*)&sW[kk][tx * 8];
        float4 b1 = *(float4*)&sW[kk][tx * 8 + 4];
        acc[0][0] += a0 * b0.x; acc[0][1] += a0 * b0.y; acc[0][2] += a0 * b0.z; acc[0][3] += a0 * b0.w;
        acc[0][4] += a0 * b1.x; acc[0][5] += a0 * b1.y; acc[0][6] += a0 * b1.z; acc[0][7] += a0 * b1.w;
        acc[1][0] += a1 * b0.x; acc[1][1] += a1 * b0.y; acc[1][2] += a1 * b0.z; acc[1][3] += a1 * b0.w;
        acc[1][4] += a1 * b1.x; acc[1][5] += a1 * b1.y; acc[1][6] += a1 * b1.z; acc[1][7] += a1 * b1.w;
        acc[2][0] += a2 * b0.x; acc[2][1] += a2 * b0.y; acc[2][2] += a2 * b0.z; acc[2][3] += a2 * b0.w;
        acc[2][4] += a2 * b1.x; acc[2][5] += a2 * b1.y; acc[2][6] += a2 * b1.z; acc[2][7] += a2 * b1.w;
        acc[3][0] += a3 * b0.x; acc[3][1] += a3 * b0.y; acc[3][2] += a3 * b0.z; acc[3][3] += a3 * b0.w;
        acc[3][4] += a3 * b1.x; acc[3][5] += a3 * b1.y; acc[3][6] += a3 * b1.z; acc[3][7] += a3 * b1.w;
    }
#pragma unroll
    for (int i = 0; i < 4; i++) {
        int r = rowBase + ty * 4 + i;
        if (r < NN) {
            *(float4*)&g_hms[r * 128 + tx * 8]     = make_float4(acc[i][0], acc[i][1], acc[i][2], acc[i][3]);
            *(float4*)&g_hms[r * 128 + tx * 8 + 4] = make_float4(acc[i][4], acc[i][5], acc[i][6], acc[i][7]);
        }
    }
}

// ---------------- gather 2: mu/std/z + bf16 split --------------------------
__global__ __launch_bounds__(256) void k_gather2(const float* __restrict__ eps,
                                                 const float* __restrict__ bmu,
                                                 const float* __restrict__ bstd,
                                                 float* __restrict__ out) {
    int node = blockIdx.x * 8 + (threadIdx.x >> 5);
    if (node >= NN) return;
    int lane = threadIdx.x & 31;
    int beg = g_off[node];
    int cnt = g_cin[node];
    float m0 = 0.f, m1 = 0.f, v0 = 0.f, v1 = 0.f;
    int j = 0;
    for (; j + 2 <= cnt; j += 2) {
        int s0 = g_esrc[beg + j];
        int s1 = g_esrc[beg + j + 1];
        const float* p0 = &g_hms[s0 * 128];
        const float* p1 = &g_hms[s1 * 128];
        m0 += p0[lane];       m1 += p0[32 + lane];
        v0 += p0[64 + lane];  v1 += p0[96 + lane];
        m0 += p1[lane];       m1 += p1[32 + lane];
        v0 += p1[64 + lane];  v1 += p1[96 + lane];
    }
    for (; j < cnt; j++) {
        int s = g_esrc[beg + j];
        const float* p = &g_hms[s * 128];
        m0 += p[lane];       m1 += p[32 + lane];
        v0 += p[64 + lane];  v1 += p[96 + lane];
    }
    float si = g_sin[node];
    float mu0 = m0 * si + bmu[lane];
    float mu1 = m1 * si + bmu[lane + 32];
    float st0 = __expf(v0 * si + bstd[lane]);
    float st1 = __expf(v1 * si + bstd[lane + 32]);
    out[MU_OFF + (size_t)node * F + lane]       = mu0;
    out[MU_OFF + (size_t)node * F + 32 + lane]  = mu1;
    out[STD_OFF + (size_t)node * F + lane]      = st0;
    out[STD_OFF + (size_t)node * F + 32 + lane] = st1;
    float z0 = eps[node * F + lane]      * st0 + mu0;
    float z1 = eps[node * F + 32 + lane] * st1 + mu1;

    __nv_bfloat16 h0 = __float2bfloat16_rn(z0);
    __nv_bfloat16 h1 = __float2bfloat16_rn(z1);
    __nv_bfloat16 l0 = __float2bfloat16_rn(z0 - __bfloat162float(h0));
    __nv_bfloat16 l1 = __float2bfloat16_rn(z1 - __bfloat162float(h1));
    __nv_bfloat16* za = &g_ZA[(size_t)node * 192];
    __nv_bfloat16* zb = &g_ZB[(size_t)node * 192];
    za[lane] = h0;       za[lane + 32] = h1;
    za[64 + lane] = l0;  za[96 + lane] = l1;
    za[128 + lane] = h0; za[160 + lane] = h1;
    zb[lane] = h0;       zb[lane + 32] = h1;
    zb[64 + lane] = h0;  zb[96 + lane] = h1;
    zb[128 + lane] = l0; zb[160 + lane] = l1;
}

// ---------------- adj = sigmoid(Z Z^T), symmetric, persistent, cp.async -----
#define KW     192
#define STRDB  400                       // bytes per smem row (200 bf16)
#define TILE_BYTES (128 * STRDB)         // 51200 B
#define ADJ_SMEM   (2 * TILE_BYTES)      // 102400 B
#define NPAN   79
#define NT_UT  (NPAN * (NPAN + 1) / 2)   // 3160
#define ADJ_GRID 296
#define ADJ_CHUNK ((NT_UT + ADJ_GRID - 1) / ADJ_GRID)  // 11

// cooperative cp.async of a 128-row x 384B panel into smem (row stride 400B)
__device__ __forceinline__ void panel_cpasync(uint32_t smBase, const char* gBase,
                                              int rowBase, int tid) {
    // 3072 chunks of 16B, 128 threads -> 24 iters
#pragma unroll
    for (int it = 0; it < 24; it++) {
        int idx = tid + it * 128;
        int r = idx / 24;
        int cc = idx - r * 24;
        int grow = rowBase + r;
        const char* src = gBase + (size_t)grow * 384 + cc * 16;
        int ss = (grow < NN) ? 16 : 0;
        cpasync16(smBase + r * STRDB + cc * 16, src, ss);
    }
}

__global__ __launch_bounds__(128, 2) void k_adj_hmma(float* __restrict__ out) {
    extern __shared__ char smem[];
    char* smA = smem;
    char* smB = smem + TILE_BYTES;
    uint32_t sbA = smem_u32(smA);
    uint32_t sbB = smem_u32(smB);

    int tid = threadIdx.x;
    int wid = tid >> 5, lane = tid & 31;
    int wm = wid & 1;        // row half (64 rows)
    int wn = wid >> 1;       // col half (64 cols)
    int group = lane >> 2;
    int qp = lane & 3;
    int lrow = lane & 15;
    int lkh  = (lane >> 4) * 16;

    int t0 = blockIdx.x * ADJ_CHUNK;
    int t1 = t0 + ADJ_CHUNK; if (t1 > NT_UT) t1 = NT_UT;
    if (t0 >= NT_UT) return;

    int p = 0, base = 0;
    while (base + (NPAN - p) <= t0) { base += NPAN - p; p++; }
    int c = p + (t0 - base);

    const char* ZA = (const char*)g_ZA;
    const char* ZB = (const char*)g_ZB;

    // prologue: load A(p) and B(c)
    panel_cpasync(sbA, ZA, p * 128, tid);
    panel_cpasync(sbB, ZB, c * 128, tid);
    CP_COMMIT();
    CP_WAIT0();
    __syncthreads();

    for (int t = t0; t < t1; t++) {
        int rb = p * 128, cb = c * 128;

        float acc[4][8][4];
#pragma unroll
        for (int mt = 0; mt < 4; mt++)
#pragma unroll
            for (int nt = 0; nt < 8; nt++)
#pragma unroll
                for (int u = 0; u < 4; u++) acc[mt][nt][u] = 0.f;

#pragma unroll
        for (int ks = 0; ks < KW / 16; ks++) {
            int kb = ks * 32;
            uint32_t a[4][4];
#pragma unroll
            for (int mt = 0; mt < 4; mt++) {
                uint32_t addr = sbA + (wm * 64 + mt * 16 + lrow) * STRDB + kb + lkh;
                ldsm4(a[mt], addr);
            }
            uint32_t b[8][2];
#pragma unroll
            for (int bt = 0; bt < 4; bt++) {
                uint32_t tmp[4];
                uint32_t addr = sbB + (wn * 64 + bt * 16 + lrow) * STRDB + kb + lkh;
                ldsm4(tmp, addr);
                b[2 * bt][0] = tmp[0];     b[2 * bt][1] = tmp[2];
                b[2 * bt + 1][0] = tmp[1]; b[2 * bt + 1][1] = tmp[3];
            }
#pragma unroll
            for (int mt = 0; mt < 4; mt++)
#pragma unroll
                for (int nt = 0; nt < 8; nt++)
                    mma16816(acc[mt][nt], a[mt], b[nt]);
        }

        __syncthreads();   // all warps done reading smem

        // prefetch next tile's panels; overlaps epilogue below
        int np = p, nc = c + 1;
        if (t + 1 < t1) {
            if (nc >= NPAN) { np = p + 1; nc = np; }
            if (np != p) panel_cpasync(sbA, ZA, np * 128, tid);
            panel_cpasync(sbB, ZB, nc * 128, tid);
            CP_COMMIT();
        }

        // sigmoid once
#pragma unroll
        for (int mt = 0; mt < 4; mt++)
#pragma unroll
            for (int nt = 0; nt < 8; nt++)
#pragma unroll
                for (int u = 0; u < 4; u++) acc[mt][nt][u] = sigf(acc[mt][nt][u]);

        // direct store (rb, cb)
#pragma unroll
        for (int mt = 0; mt < 4; mt++) {
            int r0 = rb + wm * 64 + mt * 16 + group;
            int r1 = r0 + 8;
            bool ok0 = r0 < NN, ok1 = r1 < NN;
            size_t ro0 = (size_t)r0 * NN, ro1 = (size_t)r1 * NN;
#pragma unroll
            for (int nt = 0; nt < 8; nt++) {
                int col = cb + wn * 64 + nt * 8 + qp * 2;
                if (col < NN) {
                    if (ok0) *(float2*)(out + ro0 + col) = make_float2(acc[mt][nt][0], acc[mt][nt][1]);
                    if (ok1) *(float2*)(out + ro1 + col) = make_float2(acc[mt][nt][2], acc[mt][nt][3]);
                }
            }
        }
        // mirrored store (cb, rb)
        if (p != c) {
#pragma unroll
            for (int mt = 0; mt < 4; mt++) {
                int r0 = rb + wm * 64 + mt * 16 + group;
                int r1 = r0 + 8;
                bool ok0 = r0 < NN, ok1 = r1 < NN;
#pragma unroll
                for (int nt = 0; nt < 8; nt++) {
                    int col = cb + wn * 64 + nt * 8 + qp * 2;
                    if (col < NN) {
                        if (ok0) out[(size_t)col * NN + r0] = acc[mt][nt][0];
                        if (ok1) out[(size_t)col * NN + r1] = acc[mt][nt][2];
                    }
                    if (col + 1 < NN) {
                        if (ok0) out[(size_t)(col + 1) * NN + r0] = acc[mt][nt][1];
                        if (ok1) out[(size_t)(col + 1) * NN + r1] = acc[mt][nt][3];
                    }
                }
            }
        }

        p = np; c = nc;
        CP_WAIT0();
        __syncthreads();
    }
}

// ---------------- launcher -------------------------------------------------
extern "C" void kernel_launch(void* const* d_in, const int* in_sizes, int n_in,
                              void* d_out, int out_size) {
    (void)in_sizes; (void)n_in; (void)out_size;
    const float* feat = (const float*)d_in[0];
    const float* eps  = (const float*)d_in[1];
    const int*   src  = (const int*)d_in[2];
    const int*   dst  = (const int*)d_in[3];
    const float* W1   = (const float*)d_in[4];
    const float* b1   = (const float*)d_in[5];
    const float* Wmu  = (const float*)d_in[6];
    const float* bmu  = (const float*)d_in[7];
    const float* Wstd = (const float*)d_in[8];
    const float* bstd = (const float*)d_in[9];
    float* out = (float*)d_out;

    static bool init = false;
    if (!init) {
        cudaFuncSetAttribute(k_adj_hmma, cudaFuncAttributeMaxDynamicSharedMemorySize, ADJ_SMEM);
        init = true;
    }

    k_zero<<<(NN + 255) / 256, 256>>>();
    k_deg<<<NE / 256, 256>>>(src, dst);
    k_scan<<<1, 1024>>>();
    k_scatter<<<NE / 256, 256>>>(src, dst);
    k_gemm1<<<(NN + 63) / 64, 256>>>(feat, W1);
    k_gather1<<<(NN + 7) / 8, 256>>>(b1);
    k_gemm2<<<(NN + 63) / 64, 256>>>(Wmu, Wstd);
    k_gather2<<<(NN + 7) / 8, 256>>>(eps, bmu, bstd, out);
    k_adj_hmma<<<ADJ_GRID, 128, ADJ_SMEM>>>(out);
}